// round 2
// baseline (speedup 1.0000x reference)
#include <cuda_runtime.h>
#include <cuda_bf16.h>
#include <math.h>
#include <stdint.h>
#include <stddef.h>

#define BB 256
#define DD 1280
#define NN 49
#define KK 8
#define NCLS 23
#define CD 256
#define NCH 5

// ---------------- scratch (device globals) ----------------
__device__ float g_E[(size_t)BB * KK * DD];   // raw E [b][k][d]
__device__ float g_invE[BB];
__device__ float g_p[BB * DD];                // pool mean [b][d]
__device__ float g_y1[BB * 64];               // enc GEMM accum
__device__ float g_x2braw[BB * 64];           // pool GEMM accum
__device__ float g_O[(size_t)BB * 4096];      // normalized outer
__device__ float g_hraw[BB * 128];            // fc1 accum

// ---------------- K0: zero accumulators ----------------
__global__ void k0_zero() {
    int i = blockIdx.x * 256 + threadIdx.x;   // 128*256 = 32768
    if (i < BB * 64) { g_y1[i] = 0.f; g_x2braw[i] = 0.f; }
    if (i < BB * 128) g_hraw[i] = 0.f;
}

// ---------------- K1: BN + encoding + pool ----------------
// smem float offsets
#define S_SC 0
#define S_SH 1280
#define S_CC 2560            // 8*256 codeword chunk
#define S_X  4608            // 49*257
#define S_A  17204           // 49*8 (16B aligned)
#define S_X2 17596
#define S_XC 17648
#define S_AS 18040
#define S_C2 18048
#define S_SK 18056
#define S_RD 18064
#define SM1_BYTES (18072 * 4)

__global__ void __launch_bounds__(256)
k1_encode(const float* __restrict__ x,
          const float* __restrict__ g2, const float* __restrict__ b2,
          const float* __restrict__ m2, const float* __restrict__ v2,
          const float* __restrict__ cw, const float* __restrict__ sk)
{
    extern __shared__ float sm[];
    float* s_sc = sm + S_SC;
    float* s_sh = sm + S_SH;
    float* s_Cc = sm + S_CC;
    float* s_X  = sm + S_X;
    float* s_A  = sm + S_A;
    float* s_x2 = sm + S_X2;
    float* s_xc = sm + S_XC;
    float* s_as = sm + S_AS;
    float* s_c2 = sm + S_C2;
    float* s_sk = sm + S_SK;
    float* s_rd = sm + S_RD;

    const int b = blockIdx.x;
    const int tid = threadIdx.x;
    const int lane = tid & 31;
    const int w = tid >> 5;

    for (int d = tid; d < DD; d += 256) {
        float inv = g2[d] * rsqrtf(v2[d] + 1e-5f);
        s_sc[d] = inv;
        s_sh[d] = fmaf(-m2[d], inv, b2[d]);
    }
    if (tid < KK) s_sk[tid] = sk[tid];
    // c2[k]: warp k reduces over d from global
    {
        float p = 0.f;
        for (int d = lane; d < DD; d += 32) {
            float c = cw[w * DD + d];
            p = fmaf(c, c, p);
        }
        #pragma unroll
        for (int o = 16; o; o >>= 1) p += __shfl_xor_sync(0xffffffffu, p, o);
        if (lane == 0) s_c2[w] = p;
    }

    const float* xb = x + (size_t)b * (DD * NN);

    // ---- pass 1: x2[n], xc[n,k] ----
    float ax2[7];
    float axc[7][8];
    #pragma unroll
    for (int t = 0; t < 7; t++) {
        ax2[t] = 0.f;
        #pragma unroll
        for (int k = 0; k < 8; k++) axc[t][k] = 0.f;
    }

    for (int c = 0; c < NCH; c++) {
        __syncthreads();
        for (int i = tid; i < KK * CD; i += 256) {
            int k = i >> 8, dl = i & 255;
            s_Cc[i] = cw[k * DD + c * CD + dl];
        }
        const float* xp = xb + c * (CD * NN);
        for (int i = tid; i < CD * NN; i += 256) {
            int dl = i / NN;
            int n = i - dl * NN;
            int d = c * CD + dl;
            s_X[n * 257 + dl] = fmaf(xp[i], s_sc[d], s_sh[d]);
        }
        __syncthreads();
        #pragma unroll
        for (int it = 0; it < 8; it++) {
            int dl = lane + (it << 5);
            float c8[8];
            #pragma unroll
            for (int k = 0; k < 8; k++) c8[k] = s_Cc[k * 256 + dl];
            #pragma unroll
            for (int t = 0; t < 7; t++) {
                int n = w + (t << 3);
                if (n < NN) {
                    float v = s_X[n * 257 + dl];
                    ax2[t] = fmaf(v, v, ax2[t]);
                    #pragma unroll
                    for (int k = 0; k < 8; k++)
                        axc[t][k] = fmaf(v, c8[k], axc[t][k]);
                }
            }
        }
    }

    #pragma unroll
    for (int t = 0; t < 7; t++) {
        int n = w + (t << 3);
        float r0 = ax2[t];
        #pragma unroll
        for (int o = 16; o; o >>= 1) r0 += __shfl_xor_sync(0xffffffffu, r0, o);
        float rk[8];
        #pragma unroll
        for (int k = 0; k < 8; k++) {
            float rv = axc[t][k];
            #pragma unroll
            for (int o = 16; o; o >>= 1) rv += __shfl_xor_sync(0xffffffffu, rv, o);
            rk[k] = rv;
        }
        if (lane == 0 && n < NN) {
            s_x2[n] = r0;
            #pragma unroll
            for (int k = 0; k < 8; k++) s_xc[n * 8 + k] = rk[k];
        }
    }
    __syncthreads();

    // ---- softmax over k ----
    if (tid < NN) {
        int n = tid;
        float x2v = s_x2[n];
        float sl[8];
        float mx = -1e30f;
        #pragma unroll
        for (int k = 0; k < 8; k++) {
            float v = s_sk[k] * (x2v + s_c2[k] - 2.f * s_xc[n * 8 + k]);
            sl[k] = v;
            mx = fmaxf(mx, v);
        }
        float se = 0.f;
        #pragma unroll
        for (int k = 0; k < 8; k++) {
            float e = __expf(sl[k] - mx);
            sl[k] = e;
            se += e;
        }
        float inv = 1.f / se;
        #pragma unroll
        for (int k = 0; k < 8; k++) s_A[n * 8 + k] = sl[k] * inv;
    }
    __syncthreads();
    if (tid < KK) {
        float s = 0.f;
        for (int n = 0; n < NN; n++) s += s_A[n * 8 + tid];
        s_as[tid] = s;
    }

    // ---- pass 2: E, pool, sumsq ----
    float ssq = 0.f;
    for (int c = 0; c < NCH; c++) {
        __syncthreads();
        for (int i = tid; i < KK * CD; i += 256) {
            int k = i >> 8, dl = i & 255;
            s_Cc[i] = cw[k * DD + c * CD + dl];
        }
        const float* xp = xb + c * (CD * NN);
        for (int i = tid; i < CD * NN; i += 256) {
            int dl = i / NN;
            int n = i - dl * NN;
            int d = c * CD + dl;
            s_X[n * 257 + dl] = fmaf(xp[i], s_sc[d], s_sh[d]);
        }
        __syncthreads();
        const int d = c * CD + tid;
        float e[8];
        #pragma unroll
        for (int k = 0; k < 8; k++) e[k] = 0.f;
        float ps = 0.f;
        for (int n = 0; n < NN; n++) {
            float v = s_X[n * 257 + tid];
            ps += v;
            float4 a0 = *(const float4*)&s_A[n * 8];
            float4 a1 = *(const float4*)&s_A[n * 8 + 4];
            e[0] = fmaf(a0.x, v, e[0]); e[1] = fmaf(a0.y, v, e[1]);
            e[2] = fmaf(a0.z, v, e[2]); e[3] = fmaf(a0.w, v, e[3]);
            e[4] = fmaf(a1.x, v, e[4]); e[5] = fmaf(a1.y, v, e[5]);
            e[6] = fmaf(a1.z, v, e[6]); e[7] = fmaf(a1.w, v, e[7]);
        }
        g_p[b * DD + d] = ps * (1.f / 49.f);
        #pragma unroll
        for (int k = 0; k < 8; k++) {
            float ef = e[k] - s_as[k] * s_Cc[k * 256 + tid];
            g_E[((size_t)b * KK + k) * DD + d] = ef;
            ssq = fmaf(ef, ef, ssq);
        }
    }

    #pragma unroll
    for (int o = 16; o; o >>= 1) ssq += __shfl_xor_sync(0xffffffffu, ssq, o);
    if (lane == 0) s_rd[w] = ssq;
    __syncthreads();
    if (tid == 0) {
        float t = 0.f;
        #pragma unroll
        for (int i = 0; i < 8; i++) t += s_rd[i];
        g_invE[b] = 1.f / fmaxf(sqrtf(t), 1e-12f);
    }
}

// ---------------- generic split-K GEMM with atomic epilogue ----------------
// mode 0: A=g_E (scale g_invE) -> g_y1 ; 1: A=g_p -> g_x2braw ; 2: A=g_O -> g_hraw
__global__ void __launch_bounds__(256)
gemm_acc(int mode, const float* __restrict__ W,
         int lda, int ldy, int ilen)
{
    __shared__ float sA[16 * 68];
    __shared__ float sW[16 * 68];
    __shared__ float ssc[64];

    const float* A;
    float* Y;
    if (mode == 0)      { A = g_E; Y = g_y1; }
    else if (mode == 1) { A = g_p; Y = g_x2braw; }
    else                { A = g_O; Y = g_hraw; }

    const int tid = threadIdx.x;
    const int b0 = blockIdx.x * 64;
    const int i0 = blockIdx.y * ilen;
    const int j0 = blockIdx.z * 64;

    if (tid < 64) ssc[tid] = (mode == 0) ? g_invE[b0 + tid] : 1.f;

    const int bb0 = (tid & 15) * 4;
    const int jj0 = (tid >> 4) * 4;

    float acc[4][4];
    #pragma unroll
    for (int r = 0; r < 4; r++)
        #pragma unroll
        for (int c = 0; c < 4; c++) acc[r][c] = 0.f;

    for (int s = 0; s < ilen; s += 16) {
        __syncthreads();
        #pragma unroll
        for (int u = tid; u < 1024; u += 256) {
            int r = u >> 4;
            int ii = u & 15;
            sA[ii * 68 + r] = A[(size_t)(b0 + r) * lda + i0 + s + ii] * ssc[r];
            sW[ii * 68 + r] = W[(size_t)(j0 + r) * lda + i0 + s + ii];
        }
        __syncthreads();
        #pragma unroll
        for (int ii = 0; ii < 16; ii++) {
            float4 a  = *(const float4*)&sA[ii * 68 + bb0];
            float4 wv = *(const float4*)&sW[ii * 68 + jj0];
            acc[0][0] = fmaf(a.x, wv.x, acc[0][0]);
            acc[0][1] = fmaf(a.x, wv.y, acc[0][1]);
            acc[0][2] = fmaf(a.x, wv.z, acc[0][2]);
            acc[0][3] = fmaf(a.x, wv.w, acc[0][3]);
            acc[1][0] = fmaf(a.y, wv.x, acc[1][0]);
            acc[1][1] = fmaf(a.y, wv.y, acc[1][1]);
            acc[1][2] = fmaf(a.y, wv.z, acc[1][2]);
            acc[1][3] = fmaf(a.y, wv.w, acc[1][3]);
            acc[2][0] = fmaf(a.z, wv.x, acc[2][0]);
            acc[2][1] = fmaf(a.z, wv.y, acc[2][1]);
            acc[2][2] = fmaf(a.z, wv.z, acc[2][2]);
            acc[2][3] = fmaf(a.z, wv.w, acc[2][3]);
            acc[3][0] = fmaf(a.w, wv.x, acc[3][0]);
            acc[3][1] = fmaf(a.w, wv.y, acc[3][1]);
            acc[3][2] = fmaf(a.w, wv.z, acc[3][2]);
            acc[3][3] = fmaf(a.w, wv.w, acc[3][3]);
        }
    }
    #pragma unroll
    for (int r = 0; r < 4; r++)
        #pragma unroll
        for (int c = 0; c < 4; c++)
            atomicAdd(&Y[(size_t)(b0 + bb0 + r) * ldy + j0 + jj0 + c], acc[r][c]);
}

// ---------------- K35: x1, x2b(BN), norms, normalized outer ----------------
__global__ void __launch_bounds__(256)
k35_outer(const float* __restrict__ enc_b, const float* __restrict__ pool_b,
          const float* __restrict__ g1, const float* __restrict__ be1,
          const float* __restrict__ m1, const float* __restrict__ v1)
{
    __shared__ float s1[64], s2[64], srn[2];
    const int b = blockIdx.x;
    const int tid = threadIdx.x;
    const int lane = tid & 31;
    const int w = tid >> 5;

    if (tid < 64) {
        s1[tid] = g_y1[b * 64 + tid] + enc_b[tid];
        float inv = g1[tid] * rsqrtf(v1[tid] + 1e-5f);
        s2[tid] = fmaf(g_x2braw[b * 64 + tid] + pool_b[tid] - m1[tid], inv, be1[tid]);
    }
    __syncthreads();
    if (w < 2) {
        const float* src = (w == 0) ? s1 : s2;
        float v0 = src[lane], v1b = src[lane + 32];
        float ss = v0 * v0 + v1b * v1b;
        #pragma unroll
        for (int o = 16; o; o >>= 1) ss += __shfl_xor_sync(0xffffffffu, ss, o);
        if (lane == 0) srn[w] = sqrtf(ss);
    }
    __syncthreads();
    float scale = 1.f / fmaxf(srn[0] * srn[1], 1e-12f);
    for (int u = tid; u < 4096; u += 256) {
        int i = u >> 6;
        int j = u & 63;
        g_O[(size_t)b * 4096 + u] = s2[i] * s1[j] * scale;
    }
}

// ---------------- K5: fc1 bias + l2norm + fc2 ----------------
__global__ void __launch_bounds__(128)
k5_head(const float* __restrict__ fc1_b,
        const float* __restrict__ fc2_w, const float* __restrict__ fc2_b,
        float* __restrict__ out)
{
    __shared__ float s_h[128], s_rd[4], s_scale;
    const int b = blockIdx.x;
    const int tid = threadIdx.x;
    const int lane = tid & 31;
    const int w = tid >> 5;

    float hv = g_hraw[b * 128 + tid] + fc1_b[tid];
    s_h[tid] = hv;
    float ss = hv * hv;
    #pragma unroll
    for (int o = 16; o; o >>= 1) ss += __shfl_xor_sync(0xffffffffu, ss, o);
    if (lane == 0) s_rd[w] = ss;
    __syncthreads();
    if (tid == 0) {
        float t = s_rd[0] + s_rd[1] + s_rd[2] + s_rd[3];
        s_scale = 1.f / fmaxf(sqrtf(t), 1e-12f);
    }
    __syncthreads();
    if (tid < NCLS) {
        float sc = s_scale;
        float acc = 0.f;
        const float* wr = fc2_w + tid * 128;
        #pragma unroll 8
        for (int i = 0; i < 128; i++) acc = fmaf(s_h[i] * sc, wr[i], acc);
        out[b * NCLS + tid] = acc + fc2_b[tid];
    }
}

// ---------------- launch ----------------
extern "C" void kernel_launch(void* const* d_in, const int* in_sizes, int n_in,
                              void* d_out, int out_size) {
    const float* x      = (const float*)d_in[0];
    const float* g2     = (const float*)d_in[1];
    const float* b2     = (const float*)d_in[2];
    const float* m2     = (const float*)d_in[3];
    const float* v2     = (const float*)d_in[4];
    const float* cw     = (const float*)d_in[5];
    const float* sk     = (const float*)d_in[6];
    const float* enc_w  = (const float*)d_in[7];
    const float* enc_b  = (const float*)d_in[8];
    const float* pool_w = (const float*)d_in[9];
    const float* pool_b = (const float*)d_in[10];
    const float* g1     = (const float*)d_in[11];
    const float* be1    = (const float*)d_in[12];
    const float* m1     = (const float*)d_in[13];
    const float* v1     = (const float*)d_in[14];
    const float* fc1_w  = (const float*)d_in[15];
    const float* fc1_b  = (const float*)d_in[16];
    const float* fc2_w  = (const float*)d_in[17];
    const float* fc2_b  = (const float*)d_in[18];
    float* out = (float*)d_out;

    cudaFuncSetAttribute(k1_encode, cudaFuncAttributeMaxDynamicSharedMemorySize, SM1_BYTES);

    k0_zero<<<128, 256>>>();
    k1_encode<<<BB, 256, SM1_BYTES>>>(x, g2, b2, m2, v2, cw, sk);
    gemm_acc<<<dim3(4, 20, 1), 256>>>(0, enc_w, 10240, 64, 512);   // enc
    gemm_acc<<<dim3(4, 4, 1), 256>>>(1, pool_w, 1280, 64, 320);    // pool
    k35_outer<<<BB, 256>>>(enc_b, pool_b, g1, be1, m1, v1);
    gemm_acc<<<dim3(4, 8, 2), 256>>>(2, fc1_w, 4096, 128, 512);    // fc1
    k5_head<<<BB, 128>>>(fc1_b, fc2_w, fc2_b, out);
}

// round 3
// speedup vs baseline: 1.6511x; 1.6511x over previous
#include <cuda_runtime.h>
#include <cuda_bf16.h>
#include <math.h>
#include <stdint.h>
#include <stddef.h>

#define BB 256
#define DD 1280
#define NN 49
#define KK 8
#define NCLS 23

#define ECH 80   // enc k-chunks (ilen 128)
#define PCH 16   // pool k-chunks (ilen 80)
#define FCH 32   // fc1 k-chunks (ilen 128)

// ---------------- scratch (device globals) ----------------
__device__ float g_E[(size_t)BB * KK * DD];     // [b][k][d]
__device__ float g_p[BB * DD];                  // pool mean [b][d]
__device__ float g_x2p[5 * BB * NN];            // [c][b][n]
__device__ float g_xcp[5 * BB * NN * KK];       // [c][b][n][k]
__device__ float g_A[BB * NN * KK];             // softmax assignments
__device__ float g_as[BB * KK];                 // sum_n A
__device__ float g_ssqp[BB * 8];                // per-(b,chunk) ssq, 5 used
__device__ float g_y1p[(size_t)ECH * BB * 64];  // enc partials
__device__ float g_x2bp[(size_t)PCH * BB * 64]; // pool partials
__device__ float g_O[(size_t)BB * 4096];        // UNnormalized outer
__device__ float g_hp[(size_t)FCH * BB * 128];  // fc1 partials
__device__ float g_osc[BB];                     // outer norm scale

// ---- k1a/k1b shared-mem layout (floats) ----
#define O_X   0        // 49*257 = 12593, pad to 12596
#define O_SC  12596
#define O_SH  12852
#define O_A   13108    // k1b only: 392
#define O_AS  13500
#define O_RD  13508
#define SM_A_BYTES (13108 * 4)
#define SM_B_BYTES (13516 * 4)
#define SX(n,dl) s_X[(n) * 257 + (dl)]

// ---------------- k1a: BN + transpose + partial x2/xc + pool ----------------
__global__ void __launch_bounds__(256)
k1a(const float* __restrict__ x,
    const float* __restrict__ g2, const float* __restrict__ b2,
    const float* __restrict__ m2, const float* __restrict__ v2,
    const float* __restrict__ cw)
{
    extern __shared__ float sm[];
    float* s_X  = sm + O_X;
    float* s_sc = sm + O_SC;
    float* s_sh = sm + O_SH;

    const int b = blockIdx.x, c = blockIdx.y;
    const int tid = threadIdx.x, lane = tid & 31, w = tid >> 5;
    const int d0 = c * 256;

    {
        int d = d0 + tid;
        float inv = g2[d] * rsqrtf(v2[d] + 1e-5f);
        s_sc[tid] = inv;
        s_sh[tid] = fmaf(-m2[d], inv, b2[d]);
    }
    __syncthreads();

    const float* xp = x + ((size_t)b * DD + d0) * NN;
    for (int i = tid; i < 256 * NN; i += 256) {
        int dl = i / NN;
        int n = i - dl * NN;
        SX(n, dl) = fmaf(xp[i], s_sc[dl], s_sh[dl]);
    }
    __syncthreads();

    float ax2[7];
    float axc[7][8];
    #pragma unroll
    for (int t = 0; t < 7; t++) {
        ax2[t] = 0.f;
        #pragma unroll
        for (int k = 0; k < 8; k++) axc[t][k] = 0.f;
    }

    #pragma unroll
    for (int it = 0; it < 8; it++) {
        const int dl = lane + (it << 5);
        float c8[8];
        #pragma unroll
        for (int k = 0; k < 8; k++) c8[k] = __ldg(&cw[k * DD + d0 + dl]);
        #pragma unroll
        for (int t = 0; t < 7; t++) {
            int n = w + (t << 3);
            if (n < NN) {
                float v = SX(n, dl);
                ax2[t] = fmaf(v, v, ax2[t]);
                #pragma unroll
                for (int k = 0; k < 8; k++)
                    axc[t][k] = fmaf(v, c8[k], axc[t][k]);
            }
        }
    }

    #pragma unroll
    for (int t = 0; t < 7; t++) {
        int n = w + (t << 3);
        float r0 = ax2[t];
        #pragma unroll
        for (int o = 16; o; o >>= 1) r0 += __shfl_xor_sync(0xffffffffu, r0, o);
        float rk[8];
        #pragma unroll
        for (int k = 0; k < 8; k++) {
            float rv = axc[t][k];
            #pragma unroll
            for (int o = 16; o; o >>= 1) rv += __shfl_xor_sync(0xffffffffu, rv, o);
            rk[k] = rv;
        }
        if (lane == 0 && n < NN) {
            g_x2p[(c * BB + b) * NN + n] = r0;
            #pragma unroll
            for (int k = 0; k < 8; k++)
                g_xcp[((c * BB + b) * NN + n) * 8 + k] = rk[k];
        }
    }

    // pool partial: thread == dl, full sum over n for this chunk's d
    float ps = 0.f;
    for (int n = 0; n < NN; n++) ps += SX(n, tid);
    g_p[b * DD + d0 + tid] = ps * (1.f / 49.f);
}

// ---------------- k1s: reduce partials, softmax, asum ----------------
__global__ void __launch_bounds__(256)
k1s(const float* __restrict__ cw, const float* __restrict__ sk)
{
    __shared__ float s_c2[8], s_A[NN * 8];
    const int b = blockIdx.x, tid = threadIdx.x, lane = tid & 31, w = tid >> 5;

    {
        float p = 0.f;
        for (int d = lane; d < DD; d += 32) {
            float cv = cw[w * DD + d];
            p = fmaf(cv, cv, p);
        }
        #pragma unroll
        for (int o = 16; o; o >>= 1) p += __shfl_xor_sync(0xffffffffu, p, o);
        if (lane == 0) s_c2[w] = p;
    }
    __syncthreads();

    if (tid < NN) {
        const int n = tid;
        float x2v = 0.f;
        float xc[8];
        #pragma unroll
        for (int k = 0; k < 8; k++) xc[k] = 0.f;
        #pragma unroll
        for (int c = 0; c < 5; c++) {
            x2v += g_x2p[(c * BB + b) * NN + n];
            #pragma unroll
            for (int k = 0; k < 8; k++)
                xc[k] += g_xcp[((c * BB + b) * NN + n) * 8 + k];
        }
        float sl[8];
        float mx = -1e30f;
        #pragma unroll
        for (int k = 0; k < 8; k++) {
            float v = sk[k] * (x2v + s_c2[k] - 2.f * xc[k]);
            sl[k] = v;
            mx = fmaxf(mx, v);
        }
        float se = 0.f;
        #pragma unroll
        for (int k = 0; k < 8; k++) {
            float e = __expf(sl[k] - mx);
            sl[k] = e;
            se += e;
        }
        float inv = 1.f / se;
        #pragma unroll
        for (int k = 0; k < 8; k++) {
            float a = sl[k] * inv;
            s_A[n * 8 + k] = a;
            g_A[(size_t)b * (NN * 8) + n * 8 + k] = a;
        }
    }
    __syncthreads();
    if (tid < 8) {
        float s = 0.f;
        for (int n = 0; n < NN; n++) s += s_A[n * 8 + tid];
        g_as[b * 8 + tid] = s;
    }
}

// ---------------- k1b: E + ssq partials ----------------
__global__ void __launch_bounds__(256)
k1b(const float* __restrict__ x,
    const float* __restrict__ g2, const float* __restrict__ b2,
    const float* __restrict__ m2, const float* __restrict__ v2,
    const float* __restrict__ cw)
{
    extern __shared__ float sm[];
    float* s_X  = sm + O_X;
    float* s_sc = sm + O_SC;
    float* s_sh = sm + O_SH;
    float* s_A  = sm + O_A;
    float* s_as = sm + O_AS;
    float* s_rd = sm + O_RD;

    const int b = blockIdx.x, c = blockIdx.y;
    const int tid = threadIdx.x, lane = tid & 31, w = tid >> 5;
    const int d0 = c * 256;

    {
        int d = d0 + tid;
        float inv = g2[d] * rsqrtf(v2[d] + 1e-5f);
        s_sc[tid] = inv;
        s_sh[tid] = fmaf(-m2[d], inv, b2[d]);
    }
    for (int i = tid; i < NN * 8; i += 256) s_A[i] = g_A[(size_t)b * (NN * 8) + i];
    if (tid < 8) s_as[tid] = g_as[b * 8 + tid];
    __syncthreads();

    const float* xp = x + ((size_t)b * DD + d0) * NN;
    for (int i = tid; i < 256 * NN; i += 256) {
        int dl = i / NN;
        int n = i - dl * NN;
        SX(n, dl) = fmaf(xp[i], s_sc[dl], s_sh[dl]);
    }
    __syncthreads();

    float e[8];
    #pragma unroll
    for (int k = 0; k < 8; k++) e[k] = 0.f;
    for (int n = 0; n < NN; n++) {
        float v = SX(n, tid);
        float4 a0 = *(const float4*)&s_A[n * 8];
        float4 a1 = *(const float4*)&s_A[n * 8 + 4];
        e[0] = fmaf(a0.x, v, e[0]); e[1] = fmaf(a0.y, v, e[1]);
        e[2] = fmaf(a0.z, v, e[2]); e[3] = fmaf(a0.w, v, e[3]);
        e[4] = fmaf(a1.x, v, e[4]); e[5] = fmaf(a1.y, v, e[5]);
        e[6] = fmaf(a1.z, v, e[6]); e[7] = fmaf(a1.w, v, e[7]);
    }
    float ssq = 0.f;
    #pragma unroll
    for (int k = 0; k < 8; k++) {
        float ef = e[k] - s_as[k] * __ldg(&cw[k * DD + d0 + tid]);
        g_E[((size_t)b * 8 + k) * DD + d0 + tid] = ef;
        ssq = fmaf(ef, ef, ssq);
    }
    #pragma unroll
    for (int o = 16; o; o >>= 1) ssq += __shfl_xor_sync(0xffffffffu, ssq, o);
    if (lane == 0) s_rd[w] = ssq;
    __syncthreads();
    if (tid == 0) {
        float t = 0.f;
        #pragma unroll
        for (int i = 0; i < 8; i++) t += s_rd[i];
        g_ssqp[b * 8 + c] = t;
    }
}

// ---------------- generic split-K GEMM, partial outputs ----------------
// which 0: y<ECH -> enc chunk y; y>=ECH -> pool chunk y-ECH. which 1: fc1.
__global__ void __launch_bounds__(256)
gemm_part(int which, const float* __restrict__ W1, const float* __restrict__ W2)
{
    __shared__ float sA[16 * 68];
    __shared__ float sW[16 * 68];

    const float* A;
    const float* W;
    float* out;
    int lda, i0, ilen, j0, ldo;
    if (which == 0) {
        int y = blockIdx.y;
        if (y < ECH) {
            A = g_E;  lda = 10240; W = W1; i0 = y * 128; ilen = 128;
            out = g_y1p + (size_t)y * (BB * 64); ldo = 64; j0 = 0;
        } else {
            int c = y - ECH;
            A = g_p;  lda = 1280;  W = W2; i0 = c * 80;  ilen = 80;
            out = g_x2bp + (size_t)c * (BB * 64); ldo = 64; j0 = 0;
        }
    } else {
        int y = blockIdx.y;
        A = g_O; lda = 4096; W = W1; i0 = y * 128; ilen = 128;
        out = g_hp + (size_t)y * (BB * 128); ldo = 128; j0 = blockIdx.z * 64;
    }

    const int tid = threadIdx.x;
    const int b0 = blockIdx.x * 64;
    const int lr = tid >> 2;
    const int li4 = (tid & 3) * 4;
    const int bb0 = (tid & 15) * 4;
    const int jj0 = (tid >> 4) * 4;

    float acc[4][4];
    #pragma unroll
    for (int r = 0; r < 4; r++)
        #pragma unroll
        for (int q = 0; q < 4; q++) acc[r][q] = 0.f;

    for (int s = 0; s < ilen; s += 16) {
        __syncthreads();
        float4 av = *(const float4*)&A[(size_t)(b0 + lr) * lda + i0 + s + li4];
        float4 wv = *(const float4*)&W[(size_t)(j0 + lr) * lda + i0 + s + li4];
        sA[(li4 + 0) * 68 + lr] = av.x;
        sA[(li4 + 1) * 68 + lr] = av.y;
        sA[(li4 + 2) * 68 + lr] = av.z;
        sA[(li4 + 3) * 68 + lr] = av.w;
        sW[(li4 + 0) * 68 + lr] = wv.x;
        sW[(li4 + 1) * 68 + lr] = wv.y;
        sW[(li4 + 2) * 68 + lr] = wv.z;
        sW[(li4 + 3) * 68 + lr] = wv.w;
        __syncthreads();
        #pragma unroll
        for (int ii = 0; ii < 16; ii++) {
            float4 a  = *(const float4*)&sA[ii * 68 + bb0];
            float4 wr = *(const float4*)&sW[ii * 68 + jj0];
            acc[0][0] = fmaf(a.x, wr.x, acc[0][0]);
            acc[0][1] = fmaf(a.x, wr.y, acc[0][1]);
            acc[0][2] = fmaf(a.x, wr.z, acc[0][2]);
            acc[0][3] = fmaf(a.x, wr.w, acc[0][3]);
            acc[1][0] = fmaf(a.y, wr.x, acc[1][0]);
            acc[1][1] = fmaf(a.y, wr.y, acc[1][1]);
            acc[1][2] = fmaf(a.y, wr.z, acc[1][2]);
            acc[1][3] = fmaf(a.y, wr.w, acc[1][3]);
            acc[2][0] = fmaf(a.z, wr.x, acc[2][0]);
            acc[2][1] = fmaf(a.z, wr.y, acc[2][1]);
            acc[2][2] = fmaf(a.z, wr.z, acc[2][2]);
            acc[2][3] = fmaf(a.z, wr.w, acc[2][3]);
            acc[3][0] = fmaf(a.w, wr.x, acc[3][0]);
            acc[3][1] = fmaf(a.w, wr.y, acc[3][1]);
            acc[3][2] = fmaf(a.w, wr.z, acc[3][2]);
            acc[3][3] = fmaf(a.w, wr.w, acc[3][3]);
        }
    }
    #pragma unroll
    for (int r = 0; r < 4; r++) {
        float4 v = make_float4(acc[r][0], acc[r][1], acc[r][2], acc[r][3]);
        *(float4*)&out[(size_t)(b0 + bb0 + r) * ldo + j0 + jj0] = v;
    }
}

// ---------------- k35: reduce partials, x1/x2b, outer ----------------
__global__ void __launch_bounds__(256)
k35(const float* __restrict__ enc_b, const float* __restrict__ pool_b,
    const float* __restrict__ g1, const float* __restrict__ be1,
    const float* __restrict__ m1, const float* __restrict__ v1)
{
    __shared__ float s1[64], s2[64], srn[2], s_inv;
    const int b = blockIdx.x, tid = threadIdx.x, lane = tid & 31, w = tid >> 5;

    if (tid == 0) {
        float t = 0.f;
        #pragma unroll
        for (int c = 0; c < 5; c++) t += g_ssqp[b * 8 + c];
        s_inv = 1.f / fmaxf(sqrtf(t), 1e-12f);
    }
    float accY = 0.f, accP = 0.f;
    if (tid < 64) {
        for (int c = 0; c < ECH; c++) accY += g_y1p[(size_t)c * (BB * 64) + b * 64 + tid];
        #pragma unroll
        for (int c = 0; c < PCH; c++) accP += g_x2bp[(size_t)c * (BB * 64) + b * 64 + tid];
    }
    __syncthreads();
    if (tid < 64) {
        s1[tid] = fmaf(accY, s_inv, enc_b[tid]);
        float invbn = g1[tid] * rsqrtf(v1[tid] + 1e-5f);
        s2[tid] = fmaf(accP + pool_b[tid] - m1[tid], invbn, be1[tid]);
    }
    __syncthreads();
    if (w < 2) {
        const float* src = (w == 0) ? s1 : s2;
        float v0 = src[lane], v1b = src[lane + 32];
        float ss = v0 * v0 + v1b * v1b;
        #pragma unroll
        for (int o = 16; o; o >>= 1) ss += __shfl_xor_sync(0xffffffffu, ss, o);
        if (lane == 0) srn[w] = sqrtf(ss);
    }
    __syncthreads();
    if (tid == 0) g_osc[b] = 1.f / fmaxf(srn[0] * srn[1], 1e-12f);
    for (int u = tid; u < 4096; u += 256) {
        int i = u >> 6;
        int j = u & 63;
        g_O[(size_t)b * 4096 + u] = s2[i] * s1[j];
    }
}

// ---------------- k5: reduce fc1 partials + l2norm + fc2 ----------------
__global__ void __launch_bounds__(128)
k5(const float* __restrict__ fc1_b,
   const float* __restrict__ fc2_w, const float* __restrict__ fc2_b,
   float* __restrict__ out)
{
    __shared__ float s_h[128], s_rd[4], s_scale;
    const int b = blockIdx.x, tid = threadIdx.x, lane = tid & 31, w = tid >> 5;

    float acc = 0.f;
    #pragma unroll 8
    for (int c = 0; c < FCH; c++) acc += g_hp[(size_t)c * (BB * 128) + b * 128 + tid];
    float hv = fmaf(acc, g_osc[b], fc1_b[tid]);
    s_h[tid] = hv;
    float ss = hv * hv;
    #pragma unroll
    for (int o = 16; o; o >>= 1) ss += __shfl_xor_sync(0xffffffffu, ss, o);
    if (lane == 0) s_rd[w] = ss;
    __syncthreads();
    if (tid == 0) {
        float t = s_rd[0] + s_rd[1] + s_rd[2] + s_rd[3];
        s_scale = 1.f / fmaxf(sqrtf(t), 1e-12f);
    }
    __syncthreads();
    if (tid < NCLS) {
        float sc = s_scale;
        float a2 = 0.f;
        const float* wr = fc2_w + tid * 128;
        #pragma unroll 8
        for (int i = 0; i < 128; i++) a2 = fmaf(s_h[i] * sc, wr[i], a2);
        out[b * NCLS + tid] = a2 + fc2_b[tid];
    }
}

// ---------------- launch ----------------
extern "C" void kernel_launch(void* const* d_in, const int* in_sizes, int n_in,
                              void* d_out, int out_size) {
    const float* x      = (const float*)d_in[0];
    const float* g2     = (const float*)d_in[1];
    const float* b2     = (const float*)d_in[2];
    const float* m2     = (const float*)d_in[3];
    const float* v2     = (const float*)d_in[4];
    const float* cw     = (const float*)d_in[5];
    const float* sk     = (const float*)d_in[6];
    const float* enc_w  = (const float*)d_in[7];
    const float* enc_b  = (const float*)d_in[8];
    const float* pool_w = (const float*)d_in[9];
    const float* pool_b = (const float*)d_in[10];
    const float* g1     = (const float*)d_in[11];
    const float* be1    = (const float*)d_in[12];
    const float* m1     = (const float*)d_in[13];
    const float* v1     = (const float*)d_in[14];
    const float* fc1_w  = (const float*)d_in[15];
    const float* fc1_b  = (const float*)d_in[16];
    const float* fc2_w  = (const float*)d_in[17];
    const float* fc2_b  = (const float*)d_in[18];
    float* out = (float*)d_out;

    cudaFuncSetAttribute(k1a, cudaFuncAttributeMaxDynamicSharedMemorySize, SM_A_BYTES);
    cudaFuncSetAttribute(k1b, cudaFuncAttributeMaxDynamicSharedMemorySize, SM_B_BYTES);

    k1a<<<dim3(BB, 5), 256, SM_A_BYTES>>>(x, g2, b2, m2, v2, cw);
    k1s<<<BB, 256>>>(cw, sk);
    k1b<<<dim3(BB, 5), 256, SM_B_BYTES>>>(x, g2, b2, m2, v2, cw);
    gemm_part<<<dim3(4, ECH + PCH, 1), 256>>>(0, enc_w, pool_w);
    k35<<<BB, 256>>>(enc_b, pool_b, g1, be1, m1, v1);
    gemm_part<<<dim3(4, FCH, 2), 256>>>(1, fc1_w, nullptr);
    k5<<<BB, 128>>>(fc1_b, fc2_w, fc2_b, out);
}